// round 11
// baseline (speedup 1.0000x reference)
#include <cuda_runtime.h>
#include <cuda_bf16.h>
#include <cstdint>
#include <cfloat>

// ---------------- problem constants ----------------
#define BATCH   16384
#define NWIN    32
#define DIM     64
#define KCODES  512
#define WINDOWS (BATCH * NWIN)                // 524288
#define ZQ_ELEMS ((long long)WINDOWS * DIM)   // 33554432
#define MTILE   128
#define NTILES  (WINDOWS / MTILE)             // 4096
#define GRID    148
#define TPB     128

#define SE      72     // row stride (elements): 64 data + 8 pad -> 144B rows
#define SB      144    // row stride bytes

// ---------------- device globals (zero-initialized) ----------------
__device__ double g_loss_sum;
__device__ int    g_counts[KCODES];
__device__ float  g_norms[KCODES];
__device__ __nv_bfloat16 g_cb_hi[KCODES * SE];  // [-2e]_hi | 0 pad
__device__ __nv_bfloat16 g_cb_lo[KCODES * SE];  // [-2e]_lo | 0 pad

// ---------------- smem layout (bytes) ----------------
#define AH_OFF   0                      // 128 x 144 = 18432
#define AL_OFF   18432
#define BH_OFF   36864                  // 512 x 144 = 73728
#define BL_OFF   110592
#define NORM_OFF 184320                 // 512 f32
#define ARG_OFF  186368                 // 128 x float4
#define HIST_OFF 188416                 // 512 i32
#define RED_OFF  190464                 // 8 f32
#define SMEM_BYTES 190496

// ---------------- PTX primitives ----------------
__device__ __forceinline__ uint32_t smem_u32(const void* p) {
    uint32_t a;
    asm("{ .reg .u64 t; cvta.to.shared.u64 t, %1; cvt.u32.u64 %0, t; }"
        : "=r"(a) : "l"(p));
    return a;
}
__device__ __forceinline__ void ldsm_x4(uint32_t (&r)[4], uint32_t addr) {
    asm volatile("ldmatrix.sync.aligned.m8n8.x4.shared.b16 {%0,%1,%2,%3}, [%4];"
                 : "=r"(r[0]), "=r"(r[1]), "=r"(r[2]), "=r"(r[3]) : "r"(addr));
}
__device__ __forceinline__ void mma16816(float (&d)[4], const uint32_t (&a)[4],
                                         uint32_t b0, uint32_t b1) {
    asm volatile("mma.sync.aligned.m16n8k16.row.col.f32.bf16.bf16.f32 "
                 "{%0,%1,%2,%3}, {%4,%5,%6,%7}, {%8,%9}, {%0,%1,%2,%3};"
                 : "+f"(d[0]), "+f"(d[1]), "+f"(d[2]), "+f"(d[3])
                 : "r"(a[0]), "r"(a[1]), "r"(a[2]), "r"(a[3]), "r"(b0), "r"(b1));
}

// top-2 merge across a shfl partner (tie -> lower index)
__device__ __forceinline__ void merge2(float& b1, int& i1, float& b2, int& i2, int d) {
    float ob1 = __shfl_xor_sync(0xffffffffu, b1, d);
    int   oi1 = __shfl_xor_sync(0xffffffffu, i1, d);
    float ob2 = __shfl_xor_sync(0xffffffffu, b2, d);
    int   oi2 = __shfl_xor_sync(0xffffffffu, i2, d);
    bool afirst = (b1 < ob1) || (b1 == ob1 && i1 < oi1);
    float s1 = afirst ? b1 : ob1;   int t1 = afirst ? i1 : oi1;
    float ca = afirst ? b2 : ob2;   int ia = afirst ? i2 : oi2;  // winner's 2nd
    float cv = afirst ? ob1 : b1;   int ib = afirst ? oi1 : i1;  // loser's 1st
    bool sa = (ca < cv) || (ca == cv && ia < ib);
    b1 = s1; i1 = t1;
    b2 = sa ? ca : cv; i2 = sa ? ia : ib;
}

// ---------------- prep: parallel norms + scaled/split codebook ----------------
__global__ void vq_prep_kernel(const float* __restrict__ cb) {
    const int k = blockIdx.x;    // 512 blocks
    const int d = threadIdx.x;   // 64 threads
    __shared__ float ws[2];
    if (k == 0 && d == 0) g_loss_sum = 0.0;
    if (d == 0) g_counts[k] = 0;

    float x = cb[k * DIM + d];
    float b = -2.f * x;
    __nv_bfloat16 h = __float2bfloat16(b);
    g_cb_hi[k * SE + d] = h;
    g_cb_lo[k * SE + d] = __float2bfloat16(b - __bfloat162float(h));

    float s = x * x;
#pragma unroll
    for (int o = 16; o > 0; o >>= 1) s += __shfl_xor_sync(0xffffffffu, s, o);
    if ((d & 31) == 0) ws[d >> 5] = s;
    __syncthreads();
    if (d == 0) g_norms[k] = ws[0] + ws[1];
}

// ---------------- main persistent mma.sync kernel ----------------
__global__ void __launch_bounds__(TPB, 1)
vq_mma_kernel(const float* __restrict__ ze, const float* __restrict__ cb,
              float* __restrict__ out, long long idx_off, long long zq_off) {
    extern __shared__ char sm[];
    const uint32_t smb = smem_u32(sm);
    __nv_bfloat16* sAh = (__nv_bfloat16*)(sm + AH_OFF);
    __nv_bfloat16* sAl = (__nv_bfloat16*)(sm + AL_OFF);
    float*  snorm  = (float*)(sm + NORM_OFF);
    float4* argbuf = (float4*)(sm + ARG_OFF);
    int*    shist  = (int*)(sm + HIST_OFF);
    float*  sred   = (float*)(sm + RED_OFF);

    const int tid  = threadIdx.x;
    const int wid  = tid >> 5;
    const int lane = tid & 31;
    const int q    = lane & 3;
    const int g    = lane >> 2;
    const int m0   = wid * 32;

    // ldmatrix lane address offsets
    const int a_row = (lane & 7) + (((lane >> 3) & 1) << 3);
    const int a_k   = ((lane >> 4) & 1) << 3;
    const int b_row = (lane & 7) + (((lane >> 4) & 1) << 3);
    const int b_k   = ((lane >> 3) & 1) << 3;

    // one-time: hist zero, norms, codebook stage
    for (int k = tid; k < KCODES; k += TPB) { shist[k] = 0; snorm[k] = g_norms[k]; }
    {
        const uint4* gh = (const uint4*)g_cb_hi;  // 512*144/16 = 4608
        const uint4* gl = (const uint4*)g_cb_lo;
        uint4* dh = (uint4*)(sm + BH_OFF);
        uint4* dl = (uint4*)(sm + BL_OFF);
#pragma unroll 4
        for (int j = tid; j < 4608; j += TPB) { dh[j] = gh[j]; dl[j] = gl[j]; }
    }
    __syncthreads();

    // per-thread ldmatrix base addresses
    const uint32_t aH_base = smb + AH_OFF + (uint32_t)(m0 + a_row) * SB + a_k * 2u;
    const uint32_t aL_base = smb + AL_OFF + (uint32_t)(m0 + a_row) * SB + a_k * 2u;
    const uint32_t bH_base = smb + BH_OFF + (uint32_t)b_row * SB + b_k * 2u;
    const uint32_t bL_base = smb + BL_OFF + (uint32_t)b_row * SB + b_k * 2u;

    float lsum = 0.f;

    for (int tile = blockIdx.x; tile < NTILES; tile += gridDim.x) {
        const long long w = (long long)tile * MTILE + tid;

        // ---- convert this thread's z row into A hi/lo (64 data cols) ----
        {
            const float4* zp = (const float4*)(ze + w * DIM);
            __nv_bfloat16* ah = sAh + tid * SE;
            __nv_bfloat16* al = sAl + tid * SE;
#pragma unroll
            for (int i = 0; i < 8; i++) {  // 8 floats -> 8 bf16 (16B) per iter
                float4 v0 = zp[2 * i], v1 = zp[2 * i + 1];
                float x[8] = {v0.x, v0.y, v0.z, v0.w, v1.x, v1.y, v1.z, v1.w};
                uint32_t hw[4], lw[4];
#pragma unroll
                for (int p = 0; p < 4; p++) {
                    __nv_bfloat16 h0 = __float2bfloat16(x[2 * p]);
                    __nv_bfloat16 h1 = __float2bfloat16(x[2 * p + 1]);
                    __nv_bfloat162 hh = __halves2bfloat162(h0, h1);
                    __nv_bfloat162 ll = __halves2bfloat162(
                        __float2bfloat16(x[2 * p]     - __bfloat162float(h0)),
                        __float2bfloat16(x[2 * p + 1] - __bfloat162float(h1)));
                    hw[p] = *(uint32_t*)&hh;
                    lw[p] = *(uint32_t*)&ll;
                }
                *(uint4*)(ah + i * 8) = make_uint4(hw[0], hw[1], hw[2], hw[3]);
                *(uint4*)(al + i * 8) = make_uint4(lw[0], lw[1], lw[2], lw[3]);
            }
        }
        __syncthreads();

        // ---- cache A fragments (K = 4 blocks of 16) ----
        uint32_t aH[2][4][4], aL[2][4][4];
#pragma unroll
        for (int mt = 0; mt < 2; mt++)
#pragma unroll
            for (int kb = 0; kb < 4; kb++) {
                ldsm_x4(aH[mt][kb], aH_base + (uint32_t)mt * (16u * SB) + kb * 32u);
                ldsm_x4(aL[mt][kb], aL_base + (uint32_t)mt * (16u * SB) + kb * 32u);
            }

        // ---- score loop: 16 pairs of 16-code chunks, 8 indep. MMA chains ----
        float tb1[4] = {FLT_MAX, FLT_MAX, FLT_MAX, FLT_MAX};
        float tb2[4] = {FLT_MAX, FLT_MAX, FLT_MAX, FLT_MAX};
        int   ti1[4] = {0, 0, 0, 0};
        int   ti2[4] = {0, 0, 0, 0};

#define UPD(t, s, kk) do {                                             \
        float _s = (s); int _k = (kk);                                 \
        if (_s < tb1[t]) { tb2[t] = tb1[t]; ti2[t] = ti1[t];           \
                           tb1[t] = _s;     ti1[t] = _k; }             \
        else if (_s < tb2[t]) { tb2[t] = _s; ti2[t] = _k; }            \
    } while (0)

#pragma unroll 1
        for (int cp = 0; cp < 16; cp++) {
            const int n0 = cp * 32;
            float acc[2][2][2][4];   // [chunk][mt][nt][elem]
#pragma unroll
            for (int c = 0; c < 2; c++)
#pragma unroll
                for (int mt = 0; mt < 2; mt++)
#pragma unroll
                    for (int nt = 0; nt < 2; nt++)
#pragma unroll
                        for (int e = 0; e < 4; e++) acc[c][mt][nt][e] = 0.f;

            const uint32_t bhc = bH_base + (uint32_t)n0 * SB;
            const uint32_t blc = bL_base + (uint32_t)n0 * SB;
#pragma unroll
            for (int kb = 0; kb < 4; kb++) {
                uint32_t bh0[4], bh1[4], bl0[4], bl1[4];
                ldsm_x4(bh0, bhc + kb * 32u);
                ldsm_x4(bh1, bhc + 16u * SB + kb * 32u);
                ldsm_x4(bl0, blc + kb * 32u);
                ldsm_x4(bl1, blc + 16u * SB + kb * 32u);
#pragma unroll
                for (int mt = 0; mt < 2; mt++) {
                    mma16816(acc[0][mt][0], aH[mt][kb], bh0[0], bh0[1]);
                    mma16816(acc[0][mt][1], aH[mt][kb], bh0[2], bh0[3]);
                    mma16816(acc[1][mt][0], aH[mt][kb], bh1[0], bh1[1]);
                    mma16816(acc[1][mt][1], aH[mt][kb], bh1[2], bh1[3]);
                    mma16816(acc[0][mt][0], aL[mt][kb], bh0[0], bh0[1]);
                    mma16816(acc[0][mt][1], aL[mt][kb], bh0[2], bh0[3]);
                    mma16816(acc[1][mt][0], aL[mt][kb], bh1[0], bh1[1]);
                    mma16816(acc[1][mt][1], aL[mt][kb], bh1[2], bh1[3]);
                    mma16816(acc[0][mt][0], aH[mt][kb], bl0[0], bl0[1]);
                    mma16816(acc[0][mt][1], aH[mt][kb], bl0[2], bl0[3]);
                    mma16816(acc[1][mt][0], aH[mt][kb], bl1[0], bl1[1]);
                    mma16816(acc[1][mt][1], aH[mt][kb], bl1[2], bl1[3]);
                }
            }
            // norms (exact fp32) + register argmin update, ascending index order
#pragma unroll
            for (int c = 0; c < 2; c++)
#pragma unroll
                for (int nt = 0; nt < 2; nt++) {
                    int c0 = n0 + c * 16 + nt * 8 + 2 * q;
                    float2 nv = *(float2*)&snorm[c0];
#pragma unroll
                    for (int mt = 0; mt < 2; mt++) {
                        UPD(mt * 2 + 0, acc[c][mt][nt][0] + nv.x, c0);
                        UPD(mt * 2 + 0, acc[c][mt][nt][1] + nv.y, c0 + 1);
                        UPD(mt * 2 + 1, acc[c][mt][nt][2] + nv.x, c0);
                        UPD(mt * 2 + 1, acc[c][mt][nt][3] + nv.y, c0 + 1);
                    }
                }
        }
#undef UPD

        // ---- cross-lane top-2 merge within each quad, stash per-row result ----
#pragma unroll
        for (int t = 0; t < 4; t++) {
            merge2(tb1[t], ti1[t], tb2[t], ti2[t], 1);
            merge2(tb1[t], ti1[t], tb2[t], ti2[t], 2);
            if (q == 0) {
                int row = m0 + (t >> 1) * 16 + g + (t & 1) * 8;
                argbuf[row] = make_float4(tb1[t], __int_as_float(ti1[t]),
                                          tb2[t], __int_as_float(ti2[t]));
            }
        }
        __syncthreads();

        // ---- per-window epilogue (thread tid owns window w) ----
        float4 ar = argbuf[tid];
        float best = ar.x, best2 = ar.z;
        int   bidx = __float_as_int(ar.y), bidx2 = __float_as_int(ar.w);

        float zr[DIM];
        {
            const float4* zp = (const float4*)(ze + w * DIM);
#pragma unroll
            for (int i = 0; i < DIM / 4; i++) {
                float4 v = zp[i];
                zr[4 * i] = v.x; zr[4 * i + 1] = v.y;
                zr[4 * i + 2] = v.z; zr[4 * i + 3] = v.w;
            }
        }
        if (best2 - best < 0.0078125f) {  // exact fp32 rescue on near-tie
            float d1 = 0.f, d2 = 0.f;
            const float4* c1 = (const float4*)(cb + (size_t)bidx * DIM);
            const float4* c2 = (const float4*)(cb + (size_t)bidx2 * DIM);
#pragma unroll
            for (int i = 0; i < DIM / 4; i++) {
                float4 v1 = c1[i], v2 = c2[i];
                d1 = fmaf(v1.x, zr[4 * i], d1); d1 = fmaf(v1.y, zr[4 * i + 1], d1);
                d1 = fmaf(v1.z, zr[4 * i + 2], d1); d1 = fmaf(v1.w, zr[4 * i + 3], d1);
                d2 = fmaf(v2.x, zr[4 * i], d2); d2 = fmaf(v2.y, zr[4 * i + 1], d2);
                d2 = fmaf(v2.z, zr[4 * i + 2], d2); d2 = fmaf(v2.w, zr[4 * i + 3], d2);
            }
            float s1 = fmaf(-2.f, d1, g_norms[bidx]);
            float s2 = fmaf(-2.f, d2, g_norms[bidx2]);
            if (s2 < s1 || (s2 == s1 && bidx2 < bidx)) bidx = bidx2;
        }

        out[idx_off + w] = (float)bidx;
        atomicAdd(&shist[bidx], 1);

        {   // exact loss + zq write
            const float4* crow = (const float4*)(cb + (size_t)bidx * DIM);
            float4* zqp = (float4*)(out + zq_off + w * DIM);
#pragma unroll
            for (int i = 0; i < DIM / 4; i++) {
                float4 v = crow[i];
                float e0 = v.x - zr[4 * i],     e1 = v.y - zr[4 * i + 1];
                float e2 = v.z - zr[4 * i + 2], e3 = v.w - zr[4 * i + 3];
                lsum = fmaf(e0, e0, lsum); lsum = fmaf(e1, e1, lsum);
                lsum = fmaf(e2, e2, lsum); lsum = fmaf(e3, e3, lsum);
                zqp[i] = v;
            }
        }
        __syncthreads();  // argbuf + A tile safe for next iteration
    }

    // ---- CTA reductions: loss + histogram flush ----
#pragma unroll
    for (int o = 16; o > 0; o >>= 1) lsum += __shfl_xor_sync(0xffffffffu, lsum, o);
    if (lane == 0) sred[wid] = lsum;
    __syncthreads();
    if (tid == 0) {
        double t = (double)sred[0] + (double)sred[1] + (double)sred[2] + (double)sred[3];
        atomicAdd(&g_loss_sum, t);
    }
    for (int k = tid; k < KCODES; k += TPB)
        if (shist[k]) atomicAdd(&g_counts[k], shist[k]);
}

// ---------------- finalize: entropy + loss scalars ----------------
__global__ void vq_finalize_kernel(float* __restrict__ out, long long scal_off) {
    __shared__ double sd[KCODES];
    int t = threadIdx.x;  // 512
    float p = (float)g_counts[t] / 10.0f;
    sd[t] = (double)(p * logf(p + 1e-10f));
    __syncthreads();
#pragma unroll
    for (int s = KCODES / 2; s > 0; s >>= 1) {
        if (t < s) sd[t] += sd[t + s];
        __syncthreads();
    }
    if (t == 0) {
        float loss = (float)(g_loss_sum / (double)ZQ_ELEMS);
        out[scal_off + 0] = loss;
        out[scal_off + 1] = loss;
        out[scal_off + 2] = (float)sd[0];
    }
}

extern "C" void kernel_launch(void* const* d_in, const int* in_sizes, int n_in,
                              void* d_out, int out_size) {
    const float* ze = (const float*)d_in[0];
    const float* cb = (const float*)d_in[1];
    float* out = (float*)d_out;

    long long idx_off = 0, zq_off = WINDOWS, scal_off = (long long)WINDOWS + ZQ_ELEMS;

    static bool attr_set = false;
    if (!attr_set) {
        cudaFuncSetAttribute(vq_mma_kernel,
                             cudaFuncAttributeMaxDynamicSharedMemorySize, SMEM_BYTES);
        attr_set = true;
    }

    vq_prep_kernel<<<KCODES, DIM>>>(cb);
    vq_mma_kernel<<<GRID, TPB, SMEM_BYTES>>>(ze, cb, out, idx_off, zq_off);
    vq_finalize_kernel<<<1, KCODES>>>(out, scal_off);
}

// round 14
// speedup vs baseline: 1.9574x; 1.9574x over previous
#include <cuda_runtime.h>
#include <cuda_bf16.h>
#include <cstdint>
#include <cfloat>

// ---------------- problem constants ----------------
#define BATCH   16384
#define NWIN    32
#define DIM     64
#define KCODES  512
#define WINDOWS (BATCH * NWIN)                // 524288
#define ZQ_ELEMS ((long long)WINDOWS * DIM)   // 33554432
#define MTILE   128
#define NTILES  (WINDOWS / MTILE)             // 4096
#define GRID    148
#define TPB     256

#define SE      72     // row stride (elements): 64 data + 8 pad -> 144B rows
#define SB      144    // row stride bytes

// ---------------- device globals (zero-initialized) ----------------
__device__ double g_loss_sum;
__device__ int    g_counts[KCODES];
__device__ float  g_norms[KCODES];
__device__ __nv_bfloat16 g_cb_hi[KCODES * SE];  // [-2e]_hi | 0 pad
__device__ __nv_bfloat16 g_cb_lo[KCODES * SE];  // [-2e]_lo | 0 pad

// ---------------- smem layout (bytes) ----------------
#define AH_OFF   0                      // 128 x 144 = 18432
#define AL_OFF   18432
#define BH_OFF   36864                  // 512 x 144 = 73728
#define BL_OFF   110592
#define NORM_OFF 184320                 // 512 f32   = 2048
#define ARG_OFF  186368                 // 128 x 2 x float4 = 4096
#define HIST_OFF 190464                 // 512 i32
#define RED_OFF  192512                 // 8 f32
#define SMEM_BYTES 192544

// ---------------- PTX primitives ----------------
__device__ __forceinline__ uint32_t smem_u32(const void* p) {
    uint32_t a;
    asm("{ .reg .u64 t; cvta.to.shared.u64 t, %1; cvt.u32.u64 %0, t; }"
        : "=r"(a) : "l"(p));
    return a;
}
__device__ __forceinline__ void ldsm_x4(uint32_t (&r)[4], uint32_t addr) {
    asm volatile("ldmatrix.sync.aligned.m8n8.x4.shared.b16 {%0,%1,%2,%3}, [%4];"
                 : "=r"(r[0]), "=r"(r[1]), "=r"(r[2]), "=r"(r[3]) : "r"(addr));
}
__device__ __forceinline__ void mma16816(float (&d)[4], const uint32_t (&a)[4],
                                         uint32_t b0, uint32_t b1) {
    asm volatile("mma.sync.aligned.m16n8k16.row.col.f32.bf16.bf16.f32 "
                 "{%0,%1,%2,%3}, {%4,%5,%6,%7}, {%8,%9}, {%0,%1,%2,%3};"
                 : "+f"(d[0]), "+f"(d[1]), "+f"(d[2]), "+f"(d[3])
                 : "r"(a[0]), "r"(a[1]), "r"(a[2]), "r"(a[3]), "r"(b0), "r"(b1));
}

// top-2 merge across a shfl partner (tie -> lower index)
__device__ __forceinline__ void merge2(float& b1, int& i1, float& b2, int& i2, int d) {
    float ob1 = __shfl_xor_sync(0xffffffffu, b1, d);
    int   oi1 = __shfl_xor_sync(0xffffffffu, i1, d);
    float ob2 = __shfl_xor_sync(0xffffffffu, b2, d);
    int   oi2 = __shfl_xor_sync(0xffffffffu, i2, d);
    bool afirst = (b1 < ob1) || (b1 == ob1 && i1 < oi1);
    float s1 = afirst ? b1 : ob1;   int t1 = afirst ? i1 : oi1;
    float ca = afirst ? b2 : ob2;   int ia = afirst ? i2 : oi2;  // winner's 2nd
    float cv = afirst ? ob1 : b1;   int ib = afirst ? oi1 : i1;  // loser's 1st
    bool sa = (ca < cv) || (ca == cv && ia < ib);
    b1 = s1; i1 = t1;
    b2 = sa ? ca : cv; i2 = sa ? ia : ib;
}

// ---------------- prep: parallel norms + scaled/split codebook ----------------
__global__ void vq_prep_kernel(const float* __restrict__ cb) {
    const int k = blockIdx.x;    // 512 blocks
    const int d = threadIdx.x;   // 64 threads
    __shared__ float ws[2];
    if (k == 0 && d == 0) g_loss_sum = 0.0;
    if (d == 0) g_counts[k] = 0;

    float x = cb[k * DIM + d];
    float b = -2.f * x;
    __nv_bfloat16 h = __float2bfloat16(b);
    g_cb_hi[k * SE + d] = h;
    g_cb_lo[k * SE + d] = __float2bfloat16(b - __bfloat162float(h));

    float s = x * x;
#pragma unroll
    for (int o = 16; o > 0; o >>= 1) s += __shfl_xor_sync(0xffffffffu, s, o);
    if ((d & 31) == 0) ws[d >> 5] = s;
    __syncthreads();
    if (d == 0) g_norms[k] = ws[0] + ws[1];
}

// ---------------- main persistent mma.sync kernel (8 warps, split-N) ----------------
__global__ void __launch_bounds__(TPB, 1)
vq_mma_kernel(const float* __restrict__ ze, const float* __restrict__ cb,
              float* __restrict__ out, long long idx_off, long long zq_off) {
    extern __shared__ char sm[];
    const uint32_t smb = smem_u32(sm);
    __nv_bfloat16* sAh = (__nv_bfloat16*)(sm + AH_OFF);
    __nv_bfloat16* sAl = (__nv_bfloat16*)(sm + AL_OFF);
    float*  snorm  = (float*)(sm + NORM_OFF);
    float4* argbuf = (float4*)(sm + ARG_OFF);   // [row*2 + half]
    int*    shist  = (int*)(sm + HIST_OFF);
    float*  sred   = (float*)(sm + RED_OFF);

    const int tid   = threadIdx.x;
    const int wid   = tid >> 5;
    const int lane  = tid & 31;
    const int q     = lane & 3;
    const int g     = lane >> 2;
    const int half  = wid >> 2;       // 0: codes 0-255, 1: codes 256-511
    const int m0    = (wid & 3) * 32; // M origin of this warp

    // ldmatrix lane address offsets
    const int a_row = (lane & 7) + (((lane >> 3) & 1) << 3);
    const int a_k   = ((lane >> 4) & 1) << 3;
    const int b_row = (lane & 7) + (((lane >> 4) & 1) << 3);
    const int b_k   = ((lane >> 3) & 1) << 3;

    // one-time: hist zero, norms, codebook stage
    for (int k = tid; k < KCODES; k += TPB) { shist[k] = 0; snorm[k] = g_norms[k]; }
    {
        const uint4* gh = (const uint4*)g_cb_hi;  // 512*144/16 = 4608
        const uint4* gl = (const uint4*)g_cb_lo;
        uint4* dh = (uint4*)(sm + BH_OFF);
        uint4* dl = (uint4*)(sm + BL_OFF);
#pragma unroll 4
        for (int j = tid; j < 4608; j += TPB) { dh[j] = gh[j]; dl[j] = gl[j]; }
    }
    __syncthreads();

    // per-thread ldmatrix base addresses (B offset by this warp's code-half)
    const uint32_t aH_base = smb + AH_OFF + (uint32_t)(m0 + a_row) * SB + a_k * 2u;
    const uint32_t aL_base = smb + AL_OFF + (uint32_t)(m0 + a_row) * SB + a_k * 2u;
    const uint32_t bH_base = smb + BH_OFF + (uint32_t)(half * 256 + b_row) * SB + b_k * 2u;
    const uint32_t bL_base = smb + BL_OFF + (uint32_t)(half * 256 + b_row) * SB + b_k * 2u;

    float lsum = 0.f;

    for (int tile = blockIdx.x; tile < NTILES; tile += gridDim.x) {
        // ---- convert: 256 threads, each does half a z row (32 floats) ----
        {
            const int  row  = tid >> 1;
            const int  hoff = (tid & 1) * 32;           // element offset in row
            const long long wr = (long long)tile * MTILE + row;
            const float4* zp = (const float4*)(ze + wr * DIM + hoff);
            __nv_bfloat16* ah = sAh + row * SE + hoff;
            __nv_bfloat16* al = sAl + row * SE + hoff;
#pragma unroll
            for (int i = 0; i < 4; i++) {  // 8 floats -> 8 bf16 (16B) per iter
                float4 v0 = zp[2 * i], v1 = zp[2 * i + 1];
                float x[8] = {v0.x, v0.y, v0.z, v0.w, v1.x, v1.y, v1.z, v1.w};
                uint32_t hw[4], lw[4];
#pragma unroll
                for (int p = 0; p < 4; p++) {
                    __nv_bfloat16 h0 = __float2bfloat16(x[2 * p]);
                    __nv_bfloat16 h1 = __float2bfloat16(x[2 * p + 1]);
                    __nv_bfloat162 hh = __halves2bfloat162(h0, h1);
                    __nv_bfloat162 ll = __halves2bfloat162(
                        __float2bfloat16(x[2 * p]     - __bfloat162float(h0)),
                        __float2bfloat16(x[2 * p + 1] - __bfloat162float(h1)));
                    hw[p] = *(uint32_t*)&hh;
                    lw[p] = *(uint32_t*)&ll;
                }
                *(uint4*)(ah + i * 8) = make_uint4(hw[0], hw[1], hw[2], hw[3]);
                *(uint4*)(al + i * 8) = make_uint4(lw[0], lw[1], lw[2], lw[3]);
            }
        }
        __syncthreads();

        // ---- cache A fragments (K = 4 blocks of 16) ----
        uint32_t aH[2][4][4], aL[2][4][4];
#pragma unroll
        for (int mt = 0; mt < 2; mt++)
#pragma unroll
            for (int kb = 0; kb < 4; kb++) {
                ldsm_x4(aH[mt][kb], aH_base + (uint32_t)mt * (16u * SB) + kb * 32u);
                ldsm_x4(aL[mt][kb], aL_base + (uint32_t)mt * (16u * SB) + kb * 32u);
            }

        // ---- score loop: this warp's 256 codes = 16 chunks of 16 ----
        float tb1[4] = {FLT_MAX, FLT_MAX, FLT_MAX, FLT_MAX};
        float tb2[4] = {FLT_MAX, FLT_MAX, FLT_MAX, FLT_MAX};
        int   ti1[4] = {0, 0, 0, 0};
        int   ti2[4] = {0, 0, 0, 0};

#define UPD(t, s, kk) do {                                             \
        float _s = (s); int _k = (kk);                                 \
        if (_s < tb1[t]) { tb2[t] = tb1[t]; ti2[t] = ti1[t];           \
                           tb1[t] = _s;     ti1[t] = _k; }             \
        else if (_s < tb2[t]) { tb2[t] = _s; ti2[t] = _k; }            \
    } while (0)

#pragma unroll 1
        for (int ch = 0; ch < 16; ch++) {
            const int n0 = ch * 16;               // local to this half
            float acc[2][2][4];                   // [mt][nt][elem]
#pragma unroll
            for (int mt = 0; mt < 2; mt++)
#pragma unroll
                for (int nt = 0; nt < 2; nt++)
#pragma unroll
                    for (int e = 0; e < 4; e++) acc[mt][nt][e] = 0.f;

            const uint32_t bhc = bH_base + (uint32_t)n0 * SB;
            const uint32_t blc = bL_base + (uint32_t)n0 * SB;
#pragma unroll
            for (int kb = 0; kb < 4; kb++) {
                uint32_t bh[4], bl[4];
                ldsm_x4(bh, bhc + kb * 32u);
                ldsm_x4(bl, blc + kb * 32u);
#pragma unroll
                for (int mt = 0; mt < 2; mt++) {
                    mma16816(acc[mt][0], aH[mt][kb], bh[0], bh[1]);
                    mma16816(acc[mt][1], aH[mt][kb], bh[2], bh[3]);
                    mma16816(acc[mt][0], aL[mt][kb], bh[0], bh[1]);
                    mma16816(acc[mt][1], aL[mt][kb], bh[2], bh[3]);
                    mma16816(acc[mt][0], aH[mt][kb], bl[0], bl[1]);
                    mma16816(acc[mt][1], aH[mt][kb], bl[2], bl[3]);
                }
            }
            // norms (exact fp32) + register argmin, ascending index order
#pragma unroll
            for (int nt = 0; nt < 2; nt++) {
                int c0 = half * 256 + n0 + nt * 8 + 2 * q;
                float2 nv = *(float2*)&snorm[c0];
#pragma unroll
                for (int mt = 0; mt < 2; mt++) {
                    UPD(mt * 2 + 0, acc[mt][nt][0] + nv.x, c0);
                    UPD(mt * 2 + 0, acc[mt][nt][1] + nv.y, c0 + 1);
                    UPD(mt * 2 + 1, acc[mt][nt][2] + nv.x, c0);
                    UPD(mt * 2 + 1, acc[mt][nt][3] + nv.y, c0 + 1);
                }
            }
        }
#undef UPD

        // ---- cross-lane top-2 merge within quad, stash per-(row,half) ----
#pragma unroll
        for (int t = 0; t < 4; t++) {
            merge2(tb1[t], ti1[t], tb2[t], ti2[t], 1);
            merge2(tb1[t], ti1[t], tb2[t], ti2[t], 2);
            if (q == 0) {
                int row = m0 + (t >> 1) * 16 + g + (t & 1) * 8;
                argbuf[row * 2 + half] = make_float4(tb1[t], __int_as_float(ti1[t]),
                                                     tb2[t], __int_as_float(ti2[t]));
            }
        }
        __syncthreads();

        // ---- per-window epilogue: threads 0-127 own one window each ----
        if (tid < MTILE) {
            const long long w = (long long)tile * MTILE + tid;
            float4 a0 = argbuf[tid * 2 + 0];      // half-0 (lower indices)
            float4 a1 = argbuf[tid * 2 + 1];      // half-1
            float A1 = a0.x, A2 = a0.z, B1 = a1.x, B2 = a1.z;
            int  iA1 = __float_as_int(a0.y), iA2 = __float_as_int(a0.w);
            int  iB1 = __float_as_int(a1.y), iB2 = __float_as_int(a1.w);
            float best, best2; int bidx, bidx2;
            if (A1 <= B1) {  // tie -> half-0 (lower index)
                best = A1; bidx = iA1;
                if (A2 <= B1) { best2 = A2; bidx2 = iA2; }
                else          { best2 = B1; bidx2 = iB1; }
            } else {
                best = B1; bidx = iB1;
                if (A1 <= B2) { best2 = A1; bidx2 = iA1; }
                else          { best2 = B2; bidx2 = iB2; }
            }

            float zr[DIM];
            {
                const float4* zp = (const float4*)(ze + w * DIM);
#pragma unroll
                for (int i = 0; i < DIM / 4; i++) {
                    float4 v = zp[i];
                    zr[4 * i] = v.x; zr[4 * i + 1] = v.y;
                    zr[4 * i + 2] = v.z; zr[4 * i + 3] = v.w;
                }
            }
            if (best2 - best < 0.0078125f) {  // exact fp32 rescue on near-tie
                float d1 = 0.f, d2 = 0.f;
                const float4* c1 = (const float4*)(cb + (size_t)bidx * DIM);
                const float4* c2 = (const float4*)(cb + (size_t)bidx2 * DIM);
#pragma unroll
                for (int i = 0; i < DIM / 4; i++) {
                    float4 v1 = c1[i], v2 = c2[i];
                    d1 = fmaf(v1.x, zr[4 * i], d1); d1 = fmaf(v1.y, zr[4 * i + 1], d1);
                    d1 = fmaf(v1.z, zr[4 * i + 2], d1); d1 = fmaf(v1.w, zr[4 * i + 3], d1);
                    d2 = fmaf(v2.x, zr[4 * i], d2); d2 = fmaf(v2.y, zr[4 * i + 1], d2);
                    d2 = fmaf(v2.z, zr[4 * i + 2], d2); d2 = fmaf(v2.w, zr[4 * i + 3], d2);
                }
                float s1 = fmaf(-2.f, d1, g_norms[bidx]);
                float s2 = fmaf(-2.f, d2, g_norms[bidx2]);
                if (s2 < s1 || (s2 == s1 && bidx2 < bidx)) bidx = bidx2;
            }

            out[idx_off + w] = (float)bidx;
            atomicAdd(&shist[bidx], 1);

            {   // exact loss + zq write
                const float4* crow = (const float4*)(cb + (size_t)bidx * DIM);
                float4* zqp = (float4*)(out + zq_off + w * DIM);
#pragma unroll
                for (int i = 0; i < DIM / 4; i++) {
                    float4 v = crow[i];
                    float e0 = v.x - zr[4 * i],     e1 = v.y - zr[4 * i + 1];
                    float e2 = v.z - zr[4 * i + 2], e3 = v.w - zr[4 * i + 3];
                    lsum = fmaf(e0, e0, lsum); lsum = fmaf(e1, e1, lsum);
                    lsum = fmaf(e2, e2, lsum); lsum = fmaf(e3, e3, lsum);
                    zqp[i] = v;
                }
            }
        }
        __syncthreads();  // argbuf + A tile safe for next iteration
    }

    // ---- CTA reductions: loss + histogram flush ----
#pragma unroll
    for (int o = 16; o > 0; o >>= 1) lsum += __shfl_xor_sync(0xffffffffu, lsum, o);
    if (lane == 0) sred[wid] = lsum;
    __syncthreads();
    if (tid == 0) {
        double t = (double)sred[0] + (double)sred[1] + (double)sred[2] + (double)sred[3];
        atomicAdd(&g_loss_sum, t);   // warps 4-7 contribute 0
    }
    for (int k = tid; k < KCODES; k += TPB)
        if (shist[k]) atomicAdd(&g_counts[k], shist[k]);
}

// ---------------- finalize: entropy + loss scalars ----------------
__global__ void vq_finalize_kernel(float* __restrict__ out, long long scal_off) {
    __shared__ double sd[KCODES];
    int t = threadIdx.x;  // 512
    float p = (float)g_counts[t] / 10.0f;
    sd[t] = (double)(p * logf(p + 1e-10f));
    __syncthreads();
#pragma unroll
    for (int s = KCODES / 2; s > 0; s >>= 1) {
        if (t < s) sd[t] += sd[t + s];
        __syncthreads();
    }
    if (t == 0) {
        float loss = (float)(g_loss_sum / (double)ZQ_ELEMS);
        out[scal_off + 0] = loss;
        out[scal_off + 1] = loss;
        out[scal_off + 2] = (float)sd[0];
    }
}

extern "C" void kernel_launch(void* const* d_in, const int* in_sizes, int n_in,
                              void* d_out, int out_size) {
    const float* ze = (const float*)d_in[0];
    const float* cb = (const float*)d_in[1];
    float* out = (float*)d_out;

    long long idx_off = 0, zq_off = WINDOWS, scal_off = (long long)WINDOWS + ZQ_ELEMS;

    static bool attr_set = false;
    if (!attr_set) {
        cudaFuncSetAttribute(vq_mma_kernel,
                             cudaFuncAttributeMaxDynamicSharedMemorySize, SMEM_BYTES);
        attr_set = true;
    }

    vq_prep_kernel<<<KCODES, DIM>>>(cb);
    vq_mma_kernel<<<GRID, TPB, SMEM_BYTES>>>(ze, cb, out, idx_off, zq_off);
    vq_finalize_kernel<<<1, KCODES>>>(out, scal_off);
}

// round 15
// speedup vs baseline: 2.8263x; 1.4439x over previous
#include <cuda_runtime.h>
#include <cuda_bf16.h>
#include <cstdint>
#include <cfloat>

// ---------------- problem constants ----------------
#define BATCH   16384
#define NWIN    32
#define DIM     64
#define KCODES  512
#define WINDOWS (BATCH * NWIN)                // 524288
#define ZQ_ELEMS ((long long)WINDOWS * DIM)   // 33554432
#define MTILE   128
#define NTILES  (WINDOWS / MTILE)             // 4096
#define GRID    148
#define TPB     512

#define SE      72     // row stride (elements): 64 data + 8 pad -> 144B rows
#define SB      144    // row stride bytes

// ---------------- device globals (zero-initialized) ----------------
__device__ double g_loss_sum;
__device__ int    g_counts[KCODES];
__device__ float  g_norms[KCODES];
__device__ __nv_bfloat16 g_cb_hi[KCODES * SE];  // [-2e]_hi | 0 pad
__device__ __nv_bfloat16 g_cb_lo[KCODES * SE];  // [-2e]_lo | 0 pad

// ---------------- smem layout (bytes) ----------------
#define AH_OFF   0                      // 128 x 144 = 18432
#define AL_OFF   18432
#define BH_OFF   36864                  // 512 x 144 = 73728
#define BL_OFF   110592
#define NORM_OFF 184320                 // 512 f32  = 2048
#define ARG_OFF  186368                 // 128 x 4 x float4 = 8192
#define SIDX_OFF 194560                 // 128 i32 = 512
#define HIST_OFF 195072                 // 512 i32 = 2048
#define RED_OFF  197120                 // 16 f32
#define SMEM_BYTES 197184

// ---------------- PTX primitives ----------------
__device__ __forceinline__ uint32_t smem_u32(const void* p) {
    uint32_t a;
    asm("{ .reg .u64 t; cvta.to.shared.u64 t, %1; cvt.u32.u64 %0, t; }"
        : "=r"(a) : "l"(p));
    return a;
}
__device__ __forceinline__ void ldsm_x4(uint32_t (&r)[4], uint32_t addr) {
    asm volatile("ldmatrix.sync.aligned.m8n8.x4.shared.b16 {%0,%1,%2,%3}, [%4];"
                 : "=r"(r[0]), "=r"(r[1]), "=r"(r[2]), "=r"(r[3]) : "r"(addr));
}
__device__ __forceinline__ void mma16816(float (&d)[4], const uint32_t (&a)[4],
                                         uint32_t b0, uint32_t b1) {
    asm volatile("mma.sync.aligned.m16n8k16.row.col.f32.bf16.bf16.f32 "
                 "{%0,%1,%2,%3}, {%4,%5,%6,%7}, {%8,%9}, {%0,%1,%2,%3};"
                 : "+f"(d[0]), "+f"(d[1]), "+f"(d[2]), "+f"(d[3])
                 : "r"(a[0]), "r"(a[1]), "r"(a[2]), "r"(a[3]), "r"(b0), "r"(b1));
}

// top-2 merge across a shfl partner (tie -> lower index)
__device__ __forceinline__ void merge2(float& b1, int& i1, float& b2, int& i2, int d) {
    float ob1 = __shfl_xor_sync(0xffffffffu, b1, d);
    int   oi1 = __shfl_xor_sync(0xffffffffu, i1, d);
    float ob2 = __shfl_xor_sync(0xffffffffu, b2, d);
    int   oi2 = __shfl_xor_sync(0xffffffffu, i2, d);
    bool afirst = (b1 < ob1) || (b1 == ob1 && i1 < oi1);
    float s1 = afirst ? b1 : ob1;   int t1 = afirst ? i1 : oi1;
    float ca = afirst ? b2 : ob2;   int ia = afirst ? i2 : oi2;  // winner's 2nd
    float cv = afirst ? ob1 : b1;   int ib = afirst ? oi1 : i1;  // loser's 1st
    bool sa = (ca < cv) || (ca == cv && ia < ib);
    b1 = s1; i1 = t1;
    b2 = sa ? ca : cv; i2 = sa ? ia : ib;
}

// ---------------- prep: parallel norms + scaled/split codebook ----------------
__global__ void vq_prep_kernel(const float* __restrict__ cb) {
    const int k = blockIdx.x;    // 512 blocks
    const int d = threadIdx.x;   // 64 threads
    __shared__ float ws[2];
    if (k == 0 && d == 0) g_loss_sum = 0.0;
    if (d == 0) g_counts[k] = 0;

    float x = cb[k * DIM + d];
    float b = -2.f * x;
    __nv_bfloat16 h = __float2bfloat16(b);
    g_cb_hi[k * SE + d] = h;
    g_cb_lo[k * SE + d] = __float2bfloat16(b - __bfloat162float(h));

    float s = x * x;
#pragma unroll
    for (int o = 16; o > 0; o >>= 1) s += __shfl_xor_sync(0xffffffffu, s, o);
    if ((d & 31) == 0) ws[d >> 5] = s;
    __syncthreads();
    if (d == 0) g_norms[k] = ws[0] + ws[1];
}

// ---------------- main persistent mma.sync kernel (16 warps, quarter-N) ----------------
__global__ void __launch_bounds__(TPB, 1)
vq_mma_kernel(const float* __restrict__ ze, const float* __restrict__ cb,
              float* __restrict__ out, long long idx_off, long long zq_off) {
    extern __shared__ char sm[];
    const uint32_t smb = smem_u32(sm);
    __nv_bfloat16* sAh = (__nv_bfloat16*)(sm + AH_OFF);
    __nv_bfloat16* sAl = (__nv_bfloat16*)(sm + AL_OFF);
    float*  snorm  = (float*)(sm + NORM_OFF);
    float4* argbuf = (float4*)(sm + ARG_OFF);   // [row*4 + quarter]
    int*    sidx   = (int*)(sm + SIDX_OFF);
    int*    shist  = (int*)(sm + HIST_OFF);
    float*  sred   = (float*)(sm + RED_OFF);

    const int tid   = threadIdx.x;
    const int wid   = tid >> 5;
    const int lane  = tid & 31;
    const int q     = lane & 3;
    const int g     = lane >> 2;
    const int quarter = wid >> 2;      // code quarter: 128 codes each
    const int m0    = (wid & 3) * 32;  // M origin of this warp

    // ldmatrix lane address offsets
    const int a_row = (lane & 7) + (((lane >> 3) & 1) << 3);
    const int a_k   = ((lane >> 4) & 1) << 3;
    const int b_row = (lane & 7) + (((lane >> 4) & 1) << 3);
    const int b_k   = ((lane >> 3) & 1) << 3;

    // one-time: hist zero, norms, codebook stage
    for (int k = tid; k < KCODES; k += TPB) { shist[k] = 0; snorm[k] = g_norms[k]; }
    {
        const uint4* gh = (const uint4*)g_cb_hi;  // 512*144/16 = 4608
        const uint4* gl = (const uint4*)g_cb_lo;
        uint4* dh = (uint4*)(sm + BH_OFF);
        uint4* dl = (uint4*)(sm + BL_OFF);
#pragma unroll 4
        for (int j = tid; j < 4608; j += TPB) { dh[j] = gh[j]; dl[j] = gl[j]; }
    }
    __syncthreads();

    // per-thread ldmatrix base addresses (B offset by this warp's code quarter)
    const uint32_t aH_base = smb + AH_OFF + (uint32_t)(m0 + a_row) * SB + a_k * 2u;
    const uint32_t aL_base = smb + AL_OFF + (uint32_t)(m0 + a_row) * SB + a_k * 2u;
    const uint32_t bH_base = smb + BH_OFF + (uint32_t)(quarter * 128 + b_row) * SB + b_k * 2u;
    const uint32_t bL_base = smb + BL_OFF + (uint32_t)(quarter * 128 + b_row) * SB + b_k * 2u;

    float lsum = 0.f;

    for (int tile = blockIdx.x; tile < NTILES; tile += gridDim.x) {
        // ---- convert: 512 threads, each does a quarter z row (16 floats) ----
        {
            const int  row  = tid >> 2;
            const int  hoff = (tid & 3) * 16;           // element offset in row
            const long long wr = (long long)tile * MTILE + row;
            const float4* zp = (const float4*)(ze + wr * DIM + hoff);
            __nv_bfloat16* ah = sAh + row * SE + hoff;
            __nv_bfloat16* al = sAl + row * SE + hoff;
#pragma unroll
            for (int i = 0; i < 2; i++) {  // 8 floats -> 8 bf16 (16B) per iter
                float4 v0 = zp[2 * i], v1 = zp[2 * i + 1];
                float x[8] = {v0.x, v0.y, v0.z, v0.w, v1.x, v1.y, v1.z, v1.w};
                uint32_t hw[4], lw[4];
#pragma unroll
                for (int p = 0; p < 4; p++) {
                    __nv_bfloat16 h0 = __float2bfloat16(x[2 * p]);
                    __nv_bfloat16 h1 = __float2bfloat16(x[2 * p + 1]);
                    __nv_bfloat162 hh = __halves2bfloat162(h0, h1);
                    __nv_bfloat162 ll = __halves2bfloat162(
                        __float2bfloat16(x[2 * p]     - __bfloat162float(h0)),
                        __float2bfloat16(x[2 * p + 1] - __bfloat162float(h1)));
                    hw[p] = *(uint32_t*)&hh;
                    lw[p] = *(uint32_t*)&ll;
                }
                *(uint4*)(ah + i * 8) = make_uint4(hw[0], hw[1], hw[2], hw[3]);
                *(uint4*)(al + i * 8) = make_uint4(lw[0], lw[1], lw[2], lw[3]);
            }
        }
        __syncthreads();

        // ---- cache A fragments (K = 4 blocks of 16) ----
        uint32_t aH[2][4][4], aL[2][4][4];
#pragma unroll
        for (int mt = 0; mt < 2; mt++)
#pragma unroll
            for (int kb = 0; kb < 4; kb++) {
                ldsm_x4(aH[mt][kb], aH_base + (uint32_t)mt * (16u * SB) + kb * 32u);
                ldsm_x4(aL[mt][kb], aL_base + (uint32_t)mt * (16u * SB) + kb * 32u);
            }

        // ---- score loop: this warp's 128 codes = 8 chunks of 16 ----
        float tb1[4] = {FLT_MAX, FLT_MAX, FLT_MAX, FLT_MAX};
        float tb2[4] = {FLT_MAX, FLT_MAX, FLT_MAX, FLT_MAX};
        int   ti1[4] = {0, 0, 0, 0};
        int   ti2[4] = {0, 0, 0, 0};

#define UPD(t, s, kk) do {                                             \
        float _s = (s); int _k = (kk);                                 \
        if (_s < tb1[t]) { tb2[t] = tb1[t]; ti2[t] = ti1[t];           \
                           tb1[t] = _s;     ti1[t] = _k; }             \
        else if (_s < tb2[t]) { tb2[t] = _s; ti2[t] = _k; }            \
    } while (0)

#pragma unroll 1
        for (int ch = 0; ch < 8; ch++) {
            const int n0 = ch * 16;               // local to this quarter
            float acc[2][2][4];                   // [mt][nt][elem]
#pragma unroll
            for (int mt = 0; mt < 2; mt++)
#pragma unroll
                for (int nt = 0; nt < 2; nt++)
#pragma unroll
                    for (int e = 0; e < 4; e++) acc[mt][nt][e] = 0.f;

            const uint32_t bhc = bH_base + (uint32_t)n0 * SB;
            const uint32_t blc = bL_base + (uint32_t)n0 * SB;
#pragma unroll
            for (int kb = 0; kb < 4; kb++) {
                uint32_t bh[4], bl[4];
                ldsm_x4(bh, bhc + kb * 32u);
                ldsm_x4(bl, blc + kb * 32u);
#pragma unroll
                for (int mt = 0; mt < 2; mt++) {
                    mma16816(acc[mt][0], aH[mt][kb], bh[0], bh[1]);
                    mma16816(acc[mt][1], aH[mt][kb], bh[2], bh[3]);
                    mma16816(acc[mt][0], aL[mt][kb], bh[0], bh[1]);
                    mma16816(acc[mt][1], aL[mt][kb], bh[2], bh[3]);
                    mma16816(acc[mt][0], aH[mt][kb], bl[0], bl[1]);
                    mma16816(acc[mt][1], aH[mt][kb], bl[2], bl[3]);
                }
            }
            // norms (exact fp32) + register argmin, ascending index order
#pragma unroll
            for (int nt = 0; nt < 2; nt++) {
                int c0 = quarter * 128 + n0 + nt * 8 + 2 * q;
                float2 nv = *(float2*)&snorm[c0];
#pragma unroll
                for (int mt = 0; mt < 2; mt++) {
                    UPD(mt * 2 + 0, acc[mt][nt][0] + nv.x, c0);
                    UPD(mt * 2 + 0, acc[mt][nt][1] + nv.y, c0 + 1);
                    UPD(mt * 2 + 1, acc[mt][nt][2] + nv.x, c0);
                    UPD(mt * 2 + 1, acc[mt][nt][3] + nv.y, c0 + 1);
                }
            }
        }
#undef UPD

        // ---- cross-lane top-2 merge within quad, stash per-(row,quarter) ----
#pragma unroll
        for (int t = 0; t < 4; t++) {
            merge2(tb1[t], ti1[t], tb2[t], ti2[t], 1);
            merge2(tb1[t], ti1[t], tb2[t], ti2[t], 2);
            if (q == 0) {
                int row = m0 + (t >> 1) * 16 + g + (t & 1) * 8;
                argbuf[row * 4 + quarter] = make_float4(tb1[t], __int_as_float(ti1[t]),
                                                        tb2[t], __int_as_float(ti2[t]));
            }
        }
        __syncthreads();

        // ---- argmin finalize: threads 0-127 own one window each ----
        if (tid < MTILE) {
            const long long w = (long long)tile * MTILE + tid;
            // merge 4 quarter-top2s (quarters in ascending index order)
            float best = FLT_MAX, best2 = FLT_MAX;
            int   bidx = 0,       bidx2 = 0;
#pragma unroll
            for (int qq = 0; qq < 4; qq++) {
                float4 a = argbuf[tid * 4 + qq];
                float b1 = a.x, b2v = a.z;
                int   i1 = __float_as_int(a.y), i2v = __float_as_int(a.w);
                if (b1 < best) {
                    best2 = best; bidx2 = bidx;
                    best = b1;    bidx = i1;
                    if (b2v < best2) { best2 = b2v; bidx2 = i2v; }
                } else if (b1 < best2) {
                    best2 = b1; bidx2 = i1;
                }
            }

            if (best2 - best < 0.0078125f) {  // exact fp32 rescue on near-tie
                float zr[DIM];
                const float4* zp = (const float4*)(ze + w * DIM);
#pragma unroll
                for (int i = 0; i < DIM / 4; i++) {
                    float4 v = zp[i];
                    zr[4 * i] = v.x; zr[4 * i + 1] = v.y;
                    zr[4 * i + 2] = v.z; zr[4 * i + 3] = v.w;
                }
                float d1 = 0.f, d2 = 0.f;
                const float4* c1 = (const float4*)(cb + (size_t)bidx * DIM);
                const float4* c2 = (const float4*)(cb + (size_t)bidx2 * DIM);
#pragma unroll
                for (int i = 0; i < DIM / 4; i++) {
                    float4 v1 = c1[i], v2 = c2[i];
                    d1 = fmaf(v1.x, zr[4 * i], d1); d1 = fmaf(v1.y, zr[4 * i + 1], d1);
                    d1 = fmaf(v1.z, zr[4 * i + 2], d1); d1 = fmaf(v1.w, zr[4 * i + 3], d1);
                    d2 = fmaf(v2.x, zr[4 * i], d2); d2 = fmaf(v2.y, zr[4 * i + 1], d2);
                    d2 = fmaf(v2.z, zr[4 * i + 2], d2); d2 = fmaf(v2.w, zr[4 * i + 3], d2);
                }
                float s1 = fmaf(-2.f, d1, g_norms[bidx]);
                float s2 = fmaf(-2.f, d2, g_norms[bidx2]);
                if (s2 < s1 || (s2 == s1 && bidx2 < bidx)) bidx = bidx2;
            }

            out[idx_off + w] = (float)bidx;
            atomicAdd(&shist[bidx], 1);
            sidx[tid] = bidx;
        }
        __syncthreads();

        // ---- cooperative zq + exact loss: 4 threads per window row ----
        {
            const int row  = tid >> 2;
            const int hoff = (tid & 3) * 16;
            const long long w = (long long)tile * MTILE + row;
            const int bidx = sidx[row];
            const float4* zp   = (const float4*)(ze + w * DIM + hoff);
            const float4* crow = (const float4*)(cb + (size_t)bidx * DIM + hoff);
            float4* zqp = (float4*)(out + zq_off + w * DIM + hoff);
#pragma unroll
            for (int i = 0; i < 4; i++) {
                float4 v = crow[i];
                float4 z = zp[i];
                float e0 = v.x - z.x, e1 = v.y - z.y;
                float e2 = v.z - z.z, e3 = v.w - z.w;
                lsum = fmaf(e0, e0, lsum); lsum = fmaf(e1, e1, lsum);
                lsum = fmaf(e2, e2, lsum); lsum = fmaf(e3, e3, lsum);
                zqp[i] = v;
            }
        }
        __syncthreads();  // argbuf/sidx/A tile safe for next iteration
    }

    // ---- CTA reductions: loss + histogram flush ----
#pragma unroll
    for (int o = 16; o > 0; o >>= 1) lsum += __shfl_xor_sync(0xffffffffu, lsum, o);
    if (lane == 0) sred[wid] = lsum;
    __syncthreads();
    if (tid == 0) {
        double t = 0.0;
#pragma unroll
        for (int i = 0; i < TPB / 32; i++) t += (double)sred[i];
        atomicAdd(&g_loss_sum, t);
    }
    for (int k = tid; k < KCODES; k += TPB)
        if (shist[k]) atomicAdd(&g_counts[k], shist[k]);
}

// ---------------- finalize: entropy + loss scalars ----------------
__global__ void vq_finalize_kernel(float* __restrict__ out, long long scal_off) {
    __shared__ double sd[KCODES];
    int t = threadIdx.x;  // 512
    float p = (float)g_counts[t] / 10.0f;
    sd[t] = (double)(p * logf(p + 1e-10f));
    __syncthreads();
#pragma unroll
    for (int s = KCODES / 2; s > 0; s >>= 1) {
        if (t < s) sd[t] += sd[t + s];
        __syncthreads();
    }
    if (t == 0) {
        float loss = (float)(g_loss_sum / (double)ZQ_ELEMS);
        out[scal_off + 0] = loss;
        out[scal_off + 1] = loss;
        out[scal_off + 2] = (float)sd[0];
    }
}

extern "C" void kernel_launch(void* const* d_in, const int* in_sizes, int n_in,
                              void* d_out, int out_size) {
    const float* ze = (const float*)d_in[0];
    const float* cb = (const float*)d_in[1];
    float* out = (float*)d_out;

    long long idx_off = 0, zq_off = WINDOWS, scal_off = (long long)WINDOWS + ZQ_ELEMS;

    static bool attr_set = false;
    if (!attr_set) {
        cudaFuncSetAttribute(vq_mma_kernel,
                             cudaFuncAttributeMaxDynamicSharedMemorySize, SMEM_BYTES);
        attr_set = true;
    }

    vq_prep_kernel<<<KCODES, DIM>>>(cb);
    vq_mma_kernel<<<GRID, TPB, SMEM_BYTES>>>(ze, cb, out, idx_off, zq_off);
    vq_finalize_kernel<<<1, KCODES>>>(out, scal_off);
}